// round 7
// baseline (speedup 1.0000x reference)
#include <cuda_runtime.h>
#include <cuda_fp16.h>
#include <cstdint>

// ---------------------------------------------------------------------------
// Problem constants
// ---------------------------------------------------------------------------
#define HD    2048
#define SEQ   2048
#define NROWS 8192            // B*T
#define H4    8192            // 4*HD
#define LN_EPS 1e-5f

// GEMM tiling: 128x128 CTA tile, K-chunk 64 halves, 3-stage cp.async
#define NST 3
#define SPADH 72                          // smem row stride in halves (36 words -> banks 4g+t, conflict-free)
#define STAGE_HALVES (2 * 128 * SPADH)    // A tile + B tile = 18432 halves
#define STAGE_BYTES  (STAGE_HALVES * 2)   // 36864
#define SMEM_BYTES   (NST * STAGE_BYTES)  // 110592 (x2 CTAs = 221KB < 228KB)

// ---------------------------------------------------------------------------
// Scratch (device globals — no allocation allowed)
// ---------------------------------------------------------------------------
__device__ __align__(256) float  g_s0[(size_t)NROWS * HD];   // x1 residual
__device__ __align__(256) float  g_s2[(size_t)NROWS * HD];   // v / rr
__device__ __align__(256) float  g_s3[(size_t)NROWS * HD];   // r
__device__ __align__(256) __half g_h0[(size_t)NROWS * HD];
__device__ __align__(256) __half g_h1[(size_t)NROWS * HD];
__device__ __align__(256) __half g_h2[(size_t)NROWS * HD];
__device__ __align__(256) __half g_h3[(size_t)NROWS * HD];
__device__ __align__(256) __half g_bigh[(size_t)NROWS * H4]; // 128 MB
// fp16 weight copies
__device__ __align__(256) __half g_hWv[(size_t)HD * HD];
__device__ __align__(256) __half g_hWr[(size_t)HD * HD];
__device__ __align__(256) __half g_hWo[(size_t)HD * HD];
__device__ __align__(256) __half g_hWcr[(size_t)HD * HD];
__device__ __align__(256) __half g_hWkey[(size_t)H4 * HD];
__device__ __align__(256) __half g_hWval[(size_t)HD * H4];

// ---------------------------------------------------------------------------
// Helpers
// ---------------------------------------------------------------------------
__device__ __forceinline__ uint32_t smem_u32(const void* p) {
    uint32_t a;
    asm("{ .reg .u64 t; cvta.to.shared.u64 t, %1; cvt.u32.u64 %0, t; }"
        : "=r"(a) : "l"(p));
    return a;
}

#define MMA_F16(d, a, b)                                                     \
    asm volatile(                                                            \
        "mma.sync.aligned.m16n8k16.row.col.f32.f16.f16.f32 "                 \
        "{%0,%1,%2,%3}, {%4,%5,%6,%7}, {%8,%9}, {%0,%1,%2,%3};"              \
        : "+f"((d)[0]), "+f"((d)[1]), "+f"((d)[2]), "+f"((d)[3])             \
        : "r"((a)[0]), "r"((a)[1]), "r"((a)[2]), "r"((a)[3]),                \
          "r"((b)[0]), "r"((b)[1]))

#define CP_ASYNC16(dst, src) \
    asm volatile("cp.async.cg.shared.global [%0], [%1], 16;" :: "r"(dst), "l"(src))

__device__ __forceinline__ uint2 cvt4h(float4 v) {
    __half2 lo = __floats2half2_rn(v.x, v.y);
    __half2 hi = __floats2half2_rn(v.z, v.w);
    uint2 r;
    r.x = *(uint32_t*)&lo; r.y = *(uint32_t*)&hi;
    return r;
}

// ---------------------------------------------------------------------------
// Weight conversion fp32 -> fp16 (2 merged launches)
// ---------------------------------------------------------------------------
struct PtrTab {
    const float4* s0; const float4* s1; const float4* s2; const float4* s3;
    uint2* d0; uint2* d1; uint2* d2; uint2* d3;
};

__global__ __launch_bounds__(256) void conv_sq(PtrTab p) {
    const int idx = blockIdx.x * 256 + threadIdx.x;   // 4 x 1M float4
    const int which = idx >> 20;
    const int off = idx & 0xFFFFF;
    const float4* s; uint2* d;
    if (which == 0)      { s = p.s0; d = p.d0; }
    else if (which == 1) { s = p.s1; d = p.d1; }
    else if (which == 2) { s = p.s2; d = p.d2; }
    else                 { s = p.s3; d = p.d3; }
    d[off] = cvt4h(s[off]);
}

__global__ __launch_bounds__(256) void conv_big(const float4* __restrict__ sA,
                                                uint2* __restrict__ dA,
                                                const float4* __restrict__ sB,
                                                uint2* __restrict__ dB) {
    const int idx = blockIdx.x * 256 + threadIdx.x;   // 2 x 4M float4
    const int which = idx >> 22;
    const int off = idx & 0x3FFFFF;
    const float4* s = which ? sB : sA;
    uint2* d = which ? dB : dA;
    d[off] = cvt4h(s[off]);
}

// ---------------------------------------------------------------------------
// u = sigmoid(r) * v  -> fp16   (elementwise, 16M elems)
// ---------------------------------------------------------------------------
__global__ __launch_bounds__(256) void uew_kernel(const float4* __restrict__ V,
                                                  const float4* __restrict__ R,
                                                  uint2* __restrict__ U) {
    const int i = blockIdx.x * 256 + threadIdx.x;
    float4 v = V[i], r = R[i];
    float4 o;
    o.x = v.x / (1.f + __expf(-r.x));
    o.y = v.y / (1.f + __expf(-r.y));
    o.z = v.z / (1.f + __expf(-r.z));
    o.w = v.w / (1.f + __expf(-r.w));
    U[i] = cvt4h(o);
}

// ---------------------------------------------------------------------------
// LayerNorm + time-shift + two mixes -> fp16 outputs (feed GEMMs only)
// ---------------------------------------------------------------------------
__global__ __launch_bounds__(256) void ln_mix_kernel(
    const float* __restrict__ X, const float* __restrict__ gam,
    const float* __restrict__ bet, const float* __restrict__ mA,
    const float* __restrict__ mB, __half* __restrict__ outA,
    __half* __restrict__ outB)
{
    const int row = blockIdx.x;
    const int t   = row & (SEQ - 1);
    const int tid = threadIdx.x;
    const bool hasPrev = (t != 0);

    const float4* xr = (const float4*)(X + (size_t)row * HD);
    const float4* xp = (const float4*)(X + (size_t)(row - 1) * HD);

    float4 c[2], p[2];
    c[0] = xr[tid]; c[1] = xr[tid + 256];
    if (hasPrev) { p[0] = xp[tid]; p[1] = xp[tid + 256]; }
    else { p[0] = make_float4(0.f,0.f,0.f,0.f); p[1] = p[0]; }

    float sc = 0.f, qc = 0.f, sp = 0.f, qp = 0.f;
#pragma unroll
    for (int i = 0; i < 2; i++) {
        sc += c[i].x + c[i].y + c[i].z + c[i].w;
        qc += c[i].x*c[i].x + c[i].y*c[i].y + c[i].z*c[i].z + c[i].w*c[i].w;
        sp += p[i].x + p[i].y + p[i].z + p[i].w;
        qp += p[i].x*p[i].x + p[i].y*p[i].y + p[i].z*p[i].z + p[i].w*p[i].w;
    }
#pragma unroll
    for (int o = 16; o; o >>= 1) {
        sc += __shfl_xor_sync(0xffffffffu, sc, o);
        qc += __shfl_xor_sync(0xffffffffu, qc, o);
        sp += __shfl_xor_sync(0xffffffffu, sp, o);
        qp += __shfl_xor_sync(0xffffffffu, qp, o);
    }
    __shared__ float sm[4][8];
    __shared__ float stats[4];
    const int warp = tid >> 5, lane = tid & 31;
    if (lane == 0) { sm[0][warp]=sc; sm[1][warp]=qc; sm[2][warp]=sp; sm[3][warp]=qp; }
    __syncthreads();
    if (tid == 0) {
        float a=0.f, b2=0.f, cc=0.f, d=0.f;
#pragma unroll
        for (int i = 0; i < 8; i++) { a+=sm[0][i]; b2+=sm[1][i]; cc+=sm[2][i]; d+=sm[3][i]; }
        const float inv = 1.f / (float)HD;
        float mc = a * inv, mp = cc * inv;
        float vc = b2 * inv - mc * mc;
        float vp = d  * inv - mp * mp;
        stats[0] = mc; stats[1] = rsqrtf(vc + LN_EPS);
        stats[2] = mp; stats[3] = rsqrtf(vp + LN_EPS);
    }
    __syncthreads();
    const float mc = stats[0], rc = stats[1], mp = stats[2], rp = stats[3];

    uint2* oA = (uint2*)(outA + (size_t)row * HD);
    uint2* oB = (uint2*)(outB + (size_t)row * HD);
    const float4* g4  = (const float4*)gam;
    const float4* b4  = (const float4*)bet;
    const float4* a4  = (const float4*)mA;
    const float4* m4  = (const float4*)mB;

#pragma unroll
    for (int i = 0; i < 2; i++) {
        const int idx = tid + i * 256;
        const float4 gv = g4[idx], bv = b4[idx], av = a4[idx], mv = m4[idx];
        const float4 cv = c[i], pv = p[i];
        float4 ra, rb;
#define DO_COMP(F)                                                           \
        {                                                                    \
            float h  = (cv.F - mc) * rc * gv.F + bv.F;                       \
            float hh = hasPrev ? ((pv.F - mp) * rp * gv.F + bv.F) : 0.f;     \
            ra.F = h * av.F + hh * (1.f - av.F);                             \
            rb.F = h * mv.F + hh * (1.f - mv.F);                             \
        }
        DO_COMP(x) DO_COMP(y) DO_COMP(z) DO_COMP(w)
#undef DO_COMP
        oA[idx] = cvt4h(ra); oB[idx] = cvt4h(rb);
    }
}

// ---------------------------------------------------------------------------
// fp16 mma.sync GEMM body: C[M,N] = A[M,K] @ B[N,K]^T  (M = 8192 fixed)
// CTA 128x128x64, 3-stage cp.async, 8 warps (2x4), warp tile 64x32.
// ---------------------------------------------------------------------------
enum { EP_NONE = 0, EP_SILU = 1, EP_ADD = 3, EP_SIGB_MUL_ADD = 5 };

template <int EP, typename OutT>
__device__ __forceinline__ void gemm_body(
    const __half* __restrict__ A, const __half* __restrict__ B,
    OutT* __restrict__ C, const float* __restrict__ D,
    const float* __restrict__ E, int N, int K, int nn,
    int bid, __half* smem)
{
    const int tid  = threadIdx.x;
    const int warp = tid >> 5;
    const int lane = tid & 31;
    const int g    = lane >> 2;     // 0..7
    const int t    = lane & 3;      // 0..3
    const int wm   = warp & 1;      // 2 warps along M
    const int wn   = warp >> 1;     // 4 warps along N

    // tile mapping with GY=8 group swizzle
    const int gsz = 8 * nn;
    const int grp = bid / gsz;
    const int rem = bid % gsz;
    const int mt  = grp * 8 + (rem & 7);
    const int nt  = rem >> 3;
    const size_t brow = (size_t)mt * 128;
    const size_t bcol = (size_t)nt * 128;

    // cp.async: tile row = 128B; each thread does 4x16B for A, 4x16B for B
    const int lrow = tid >> 1;              // 0..127
    const int part = tid & 1;               // half-row: 0 or 1 (64B each)
    const __half* gA = A + (brow + lrow) * (size_t)K + part * 32;
    const __half* gB = B + (bcol + lrow) * (size_t)K + part * 32;
    const uint32_t smb = smem_u32(smem);
    const uint32_t sa_row = smb + (uint32_t)lrow * (SPADH * 2) + (uint32_t)part * 64u;
    const uint32_t sb_row = sa_row + 128u * (SPADH * 2);

    auto load_stage = [&](int s, int c) {
        const uint32_t so = (uint32_t)s * STAGE_BYTES;
        const __half* pa = gA + (size_t)c * 64;
        const __half* pb = gB + (size_t)c * 64;
#pragma unroll
        for (int j = 0; j < 4; j++) {
            CP_ASYNC16(sa_row + so + (uint32_t)(j * 16), pa + j * 8);
            CP_ASYNC16(sb_row + so + (uint32_t)(j * 16), pb + j * 8);
        }
        asm volatile("cp.async.commit_group;");
    };

    float acc[4][4][4];
#pragma unroll
    for (int i = 0; i < 4; i++)
#pragma unroll
        for (int j = 0; j < 4; j++)
#pragma unroll
            for (int r = 0; r < 4; r++) acc[i][j][r] = 0.f;

    load_stage(0, 0);
    load_stage(1, 1);

    // per-thread fragment base indices (halves)
    const int aTb = (wm * 64 + g) * SPADH + 2 * t;
    const int bTb = (wn * 32 + g) * SPADH + 2 * t;

    const int nch = K >> 6;
    for (int c = 0; c < nch; c++) {
        const int s = c % NST;
        asm volatile("cp.async.wait_group %0;" :: "n"(NST - 2));
        __syncthreads();
        if (c + 2 < nch) load_stage((c + 2) % NST, c + 2);

        const __half* sA = smem + s * STAGE_HALVES;
        const __half* sB = sA + 128 * SPADH;
#pragma unroll
        for (int ks = 0; ks < 4; ks++) {     // four k16 steps per 64-chunk
            uint32_t af[4][4], bf[4][2];
#pragma unroll
            for (int i = 0; i < 4; i++) {
                const __half* p = sA + aTb + i * (16 * SPADH) + ks * 16;
                af[i][0] = *(const uint32_t*)(p);
                af[i][1] = *(const uint32_t*)(p + 8 * SPADH);
                af[i][2] = *(const uint32_t*)(p + 8);
                af[i][3] = *(const uint32_t*)(p + 8 * SPADH + 8);
            }
#pragma unroll
            for (int j = 0; j < 4; j++) {
                const __half* p = sB + bTb + j * (8 * SPADH) + ks * 16;
                bf[j][0] = *(const uint32_t*)(p);
                bf[j][1] = *(const uint32_t*)(p + 8);
            }
#pragma unroll
            for (int i = 0; i < 4; i++)
#pragma unroll
                for (int j = 0; j < 4; j++)
                    MMA_F16(acc[i][j], af[i], bf[j]);
        }
    }
    asm volatile("cp.async.wait_group 0;");

    // ---------------- epilogue: registers -> fused ops -> stores -------------
#pragma unroll
    for (int i = 0; i < 4; i++) {
#pragma unroll
        for (int j = 0; j < 4; j++) {
            const size_t row0 = brow + wm * 64 + i * 16 + g;
            const size_t col  = bcol + wn * 32 + j * 8 + 2 * t;
#pragma unroll
            for (int h = 0; h < 2; h++) {     // h=0: rows g, h=1: rows g+8
                const size_t gi = (row0 + h * 8) * (size_t)N + col;
                float v0 = acc[i][j][2 * h + 0];
                float v1 = acc[i][j][2 * h + 1];
                float2 o;
                if (EP == EP_NONE) {
                    o = make_float2(v0, v1);
                } else if (EP == EP_SILU) {
                    o = make_float2(v0 / (1.f + __expf(-v0)),
                                    v1 / (1.f + __expf(-v1)));
                } else if (EP == EP_ADD) {
                    const float2 dv = *(const float2*)(D + gi);
                    o = make_float2(v0 + dv.x, v1 + dv.y);
                } else { // EP_SIGB_MUL_ADD: acc * sigmoid(D) + E
                    const float2 dv = *(const float2*)(D + gi);
                    const float2 ev = *(const float2*)(E + gi);
                    o = make_float2(v0 / (1.f + __expf(-dv.x)) + ev.x,
                                    v1 / (1.f + __expf(-dv.y)) + ev.y);
                }
                if (sizeof(OutT) == 2) {
                    __half2 hv = __floats2half2_rn(o.x, o.y);
                    *(__half2*)((__half*)C + gi) = hv;
                } else {
                    *(float2*)((float*)C + gi) = o;
                }
            }
        }
    }
}

template <int EP, typename OutT>
__global__ __launch_bounds__(256, 2) void gemm_mma(
    const __half* __restrict__ A, const __half* __restrict__ B,
    OutT* __restrict__ C, const float* __restrict__ D,
    const float* __restrict__ E, int N, int K, int nn)
{
    extern __shared__ __half smem[];
    gemm_body<EP, OutT>(A, B, C, D, E, N, K, nn, blockIdx.x, smem);
}

// Two independent GEMMs in one launch (cuts launch-tail bubbles).
template <int EP1, typename O1, int EP2, typename O2>
__global__ __launch_bounds__(256, 2) void gemm_dual(
    const __half* __restrict__ A1, const __half* __restrict__ B1,
    O1* __restrict__ C1, int N1, int K1, int nn1, int split,
    const __half* __restrict__ A2, const __half* __restrict__ B2,
    O2* __restrict__ C2, int N2, int K2, int nn2)
{
    extern __shared__ __half smem[];
    const int b = blockIdx.x;
    if (b < split)
        gemm_body<EP1, O1>(A1, B1, C1, nullptr, nullptr, N1, K1, nn1, b, smem);
    else
        gemm_body<EP2, O2>(A2, B2, C2, nullptr, nullptr, N2, K2, nn2, b - split, smem);
}

// ---------------------------------------------------------------------------
// Launch sequence.  (wkv_run with aa=bb=0, pp=-1e38 reduces exactly to wkv=v,
// so k / Wk / tm_first / tm_decay are dead and the Wk GEMM is skipped.)
// ---------------------------------------------------------------------------
extern "C" void kernel_launch(void* const* d_in, const int* in_sizes, int n_in,
                              void* d_out, int out_size)
{
    (void)in_sizes; (void)n_in; (void)out_size;
    const float* x     = (const float*)d_in[0];
    const float* ln1_g = (const float*)d_in[1];
    const float* ln1_b = (const float*)d_in[2];
    const float* ln2_g = (const float*)d_in[3];
    const float* ln2_b = (const float*)d_in[4];
    const float* tm_mv = (const float*)d_in[8];
    const float* tm_mr = (const float*)d_in[9];
    const float* Wv    = (const float*)d_in[11];
    const float* Wr    = (const float*)d_in[12];
    const float* Wo    = (const float*)d_in[13];
    const float* cm_mk = (const float*)d_in[14];
    const float* cm_mr = (const float*)d_in[15];
    const float* Wkey  = (const float*)d_in[16];
    const float* Wval  = (const float*)d_in[17];
    const float* Wcr   = (const float*)d_in[18];
    float* out = (float*)d_out;

    float *s0, *s2, *s3;
    __half *h0, *h1, *h2, *h3, *bigh;
    __half *hWv, *hWr, *hWo, *hWcr, *hWkey, *hWval;
    cudaGetSymbolAddress((void**)&s0, g_s0);
    cudaGetSymbolAddress((void**)&s2, g_s2);
    cudaGetSymbolAddress((void**)&s3, g_s3);
    cudaGetSymbolAddress((void**)&h0, g_h0);
    cudaGetSymbolAddress((void**)&h1, g_h1);
    cudaGetSymbolAddress((void**)&h2, g_h2);
    cudaGetSymbolAddress((void**)&h3, g_h3);
    cudaGetSymbolAddress((void**)&bigh, g_bigh);
    cudaGetSymbolAddress((void**)&hWv, g_hWv);
    cudaGetSymbolAddress((void**)&hWr, g_hWr);
    cudaGetSymbolAddress((void**)&hWo, g_hWo);
    cudaGetSymbolAddress((void**)&hWcr, g_hWcr);
    cudaGetSymbolAddress((void**)&hWkey, g_hWkey);
    cudaGetSymbolAddress((void**)&hWval, g_hWval);

    cudaFuncSetAttribute((const void*)gemm_dual<EP_NONE, float, EP_NONE, float>,
                         cudaFuncAttributeMaxDynamicSharedMemorySize, SMEM_BYTES);
    cudaFuncSetAttribute((const void*)gemm_dual<EP_SILU, __half, EP_NONE, float>,
                         cudaFuncAttributeMaxDynamicSharedMemorySize, SMEM_BYTES);
    cudaFuncSetAttribute((const void*)gemm_mma<EP_ADD, float>,
                         cudaFuncAttributeMaxDynamicSharedMemorySize, SMEM_BYTES);
    cudaFuncSetAttribute((const void*)gemm_mma<EP_SIGB_MUL_ADD, float>,
                         cudaFuncAttributeMaxDynamicSharedMemorySize, SMEM_BYTES);

    // convert weights fp32 -> fp16 (2 launches)
    PtrTab pt;
    pt.s0 = (const float4*)Wv;  pt.d0 = (uint2*)hWv;
    pt.s1 = (const float4*)Wr;  pt.d1 = (uint2*)hWr;
    pt.s2 = (const float4*)Wo;  pt.d2 = (uint2*)hWo;
    pt.s3 = (const float4*)Wcr; pt.d3 = (uint2*)hWcr;
    conv_sq<<<(4 << 20) / 256, 256>>>(pt);
    conv_big<<<(8 << 20) / 256, 256>>>((const float4*)Wkey, (uint2*)hWkey,
                                       (const float4*)Wval, (uint2*)hWval);

    const dim3 blk(256);
    const int nmT = NROWS / 128;           // 64
    const int nnSq = HD / 128;             // 16
    const int nnBg = H4 / 128;             // 64
    const int gSq = nmT * nnSq;            // 1024
    const int gBg = nmT * nnBg;            // 4096

    // --- time-mix ---
    ln_mix_kernel<<<NROWS, blk>>>(x, ln1_g, ln1_b, tm_mv, tm_mr, h0, h1);
    // v = xv@Wv^T -> s2 ; r = xr@Wr^T -> s3   (merged)
    gemm_dual<EP_NONE, float, EP_NONE, float><<<2 * gSq, blk, SMEM_BYTES>>>(
        h0, hWv, s2, HD, HD, nnSq, gSq,
        h1, hWr, s3, HD, HD, nnSq);
    // u = sigmoid(r) * v -> fp16
    uew_kernel<<<(NROWS * HD / 4) / 256, blk>>>((const float4*)s2, (const float4*)s3,
                                                (uint2*)h3);
    // x1 = u @ Wo^T + x
    gemm_mma<EP_ADD, float><<<gSq, blk, SMEM_BYTES>>>(h3, hWo, s0, x, nullptr, HD, HD, nnSq);

    // --- channel-mix ---
    ln_mix_kernel<<<NROWS, blk>>>(s0, ln2_g, ln2_b, cm_mk, cm_mr, h1, h2);
    // silu(xk2@Wkey^T) -> bigh ; rr = xr2@Wcr^T -> s2   (merged)
    gemm_dual<EP_SILU, __half, EP_NONE, float><<<gBg + gSq, blk, SMEM_BYTES>>>(
        h1, hWkey, bigh, H4, HD, nnBg, gBg,
        h2, hWcr, s2, HD, HD, nnSq);
    // out = (bigh @ Wval^T) * sigmoid(rr) + x1
    gemm_mma<EP_SIGB_MUL_ADD, float><<<gSq, blk, SMEM_BYTES>>>(
        bigh, hWval, out, s2, s0, HD, H4, nnSq);
}

// round 8
// speedup vs baseline: 1.5152x; 1.5152x over previous
#include <cuda_runtime.h>
#include <cuda_fp16.h>
#include <cstdint>

// ---------------------------------------------------------------------------
// Problem constants
// ---------------------------------------------------------------------------
#define HD    2048
#define SEQ   2048
#define NROWS 8192            // B*T
#define H4    8192            // 4*HD
#define LN_EPS 1e-5f

// GEMM tiling: 256x128 CTA tile (16 warps), K-chunk 32 halves, 3-stage cp.async
#define NST 3
#define SPADH 40                          // smem row stride in halves (conflict-free)
#define A_ROWS 256
#define B_ROWS 128
#define A_STAGE_HALVES (A_ROWS * SPADH)   // 10240
#define STAGE_HALVES ((A_ROWS + B_ROWS) * SPADH)   // 15360
#define STAGE_BYTES  (STAGE_HALVES * 2)   // 30720
#define SMEM_BYTES   (NST * STAGE_BYTES)  // 92160 (1 CTA/SM)

// ---------------------------------------------------------------------------
// Scratch (device globals — no allocation allowed)
// ---------------------------------------------------------------------------
__device__ __align__(256) float  g_s0[(size_t)NROWS * HD];
__device__ __align__(256) float  g_s2[(size_t)NROWS * HD];
__device__ __align__(256) float  g_s3[(size_t)NROWS * HD];
__device__ __align__(256) __half g_h0[(size_t)NROWS * HD];
__device__ __align__(256) __half g_h1[(size_t)NROWS * HD];
__device__ __align__(256) __half g_h2[(size_t)NROWS * HD];
__device__ __align__(256) __half g_h3[(size_t)NROWS * HD];
__device__ __align__(256) __half g_bigh[(size_t)NROWS * H4];   // 128 MB
// fp16 weight copies
__device__ __align__(256) __half g_hWv[(size_t)HD * HD];
__device__ __align__(256) __half g_hWr[(size_t)HD * HD];
__device__ __align__(256) __half g_hWo[(size_t)HD * HD];
__device__ __align__(256) __half g_hWcr[(size_t)HD * HD];
__device__ __align__(256) __half g_hWkey[(size_t)H4 * HD];
__device__ __align__(256) __half g_hWval[(size_t)HD * H4];

// ---------------------------------------------------------------------------
// Helpers
// ---------------------------------------------------------------------------
__device__ __forceinline__ uint32_t smem_u32(const void* p) {
    uint32_t a;
    asm("{ .reg .u64 t; cvta.to.shared.u64 t, %1; cvt.u32.u64 %0, t; }"
        : "=r"(a) : "l"(p));
    return a;
}

#define MMA_F16(d, a, b)                                                     \
    asm volatile(                                                            \
        "mma.sync.aligned.m16n8k16.row.col.f32.f16.f16.f32 "                 \
        "{%0,%1,%2,%3}, {%4,%5,%6,%7}, {%8,%9}, {%0,%1,%2,%3};"              \
        : "+f"((d)[0]), "+f"((d)[1]), "+f"((d)[2]), "+f"((d)[3])             \
        : "r"((a)[0]), "r"((a)[1]), "r"((a)[2]), "r"((a)[3]),                \
          "r"((b)[0]), "r"((b)[1]))

#define CP_ASYNC16(dst, src) \
    asm volatile("cp.async.cg.shared.global [%0], [%1], 16;" :: "r"(dst), "l"(src))

__device__ __forceinline__ uint2 cvt4h(float4 v) {
    __half2 lo = __floats2half2_rn(v.x, v.y);
    __half2 hi = __floats2half2_rn(v.z, v.w);
    uint2 r;
    r.x = *(uint32_t*)&lo; r.y = *(uint32_t*)&hi;
    return r;
}

// ---------------------------------------------------------------------------
// Weight conversion fp32 -> fp16 (2 merged launches)
// ---------------------------------------------------------------------------
struct PtrTab {
    const float4* s0; const float4* s1; const float4* s2; const float4* s3;
    uint2* d0; uint2* d1; uint2* d2; uint2* d3;
};

__global__ __launch_bounds__(256) void conv_sq(PtrTab p) {
    const int idx = blockIdx.x * 256 + threadIdx.x;   // 4 x 1M float4
    const int which = idx >> 20;
    const int off = idx & 0xFFFFF;
    const float4* s; uint2* d;
    if (which == 0)      { s = p.s0; d = p.d0; }
    else if (which == 1) { s = p.s1; d = p.d1; }
    else if (which == 2) { s = p.s2; d = p.d2; }
    else                 { s = p.s3; d = p.d3; }
    d[off] = cvt4h(s[off]);
}

__global__ __launch_bounds__(256) void conv_big(const float4* __restrict__ sA,
                                                uint2* __restrict__ dA,
                                                const float4* __restrict__ sB,
                                                uint2* __restrict__ dB) {
    const int idx = blockIdx.x * 256 + threadIdx.x;   // 2 x 4M float4
    const int which = idx >> 22;
    const int off = idx & 0x3FFFFF;
    const float4* s = which ? sB : sA;
    uint2* d = which ? dB : dA;
    d[off] = cvt4h(s[off]);
}

// ---------------------------------------------------------------------------
// LayerNorm + time-shift + two mixes -> fp16 outputs (feed GEMMs only)
// ---------------------------------------------------------------------------
__global__ __launch_bounds__(256) void ln_mix_kernel(
    const float* __restrict__ X, const float* __restrict__ gam,
    const float* __restrict__ bet, const float* __restrict__ mA,
    const float* __restrict__ mB, __half* __restrict__ outA,
    __half* __restrict__ outB)
{
    const int row = blockIdx.x;
    const int t   = row & (SEQ - 1);
    const int tid = threadIdx.x;
    const bool hasPrev = (t != 0);

    const float4* xr = (const float4*)(X + (size_t)row * HD);
    const float4* xp = (const float4*)(X + (size_t)(row - 1) * HD);

    float4 c[2], p[2];
    c[0] = xr[tid]; c[1] = xr[tid + 256];
    if (hasPrev) { p[0] = xp[tid]; p[1] = xp[tid + 256]; }
    else { p[0] = make_float4(0.f,0.f,0.f,0.f); p[1] = p[0]; }

    float sc = 0.f, qc = 0.f, sp = 0.f, qp = 0.f;
#pragma unroll
    for (int i = 0; i < 2; i++) {
        sc += c[i].x + c[i].y + c[i].z + c[i].w;
        qc += c[i].x*c[i].x + c[i].y*c[i].y + c[i].z*c[i].z + c[i].w*c[i].w;
        sp += p[i].x + p[i].y + p[i].z + p[i].w;
        qp += p[i].x*p[i].x + p[i].y*p[i].y + p[i].z*p[i].z + p[i].w*p[i].w;
    }
#pragma unroll
    for (int o = 16; o; o >>= 1) {
        sc += __shfl_xor_sync(0xffffffffu, sc, o);
        qc += __shfl_xor_sync(0xffffffffu, qc, o);
        sp += __shfl_xor_sync(0xffffffffu, sp, o);
        qp += __shfl_xor_sync(0xffffffffu, qp, o);
    }
    __shared__ float sm[4][8];
    __shared__ float stats[4];
    const int warp = tid >> 5, lane = tid & 31;
    if (lane == 0) { sm[0][warp]=sc; sm[1][warp]=qc; sm[2][warp]=sp; sm[3][warp]=qp; }
    __syncthreads();
    if (tid == 0) {
        float a=0.f, b2=0.f, cc=0.f, d=0.f;
#pragma unroll
        for (int i = 0; i < 8; i++) { a+=sm[0][i]; b2+=sm[1][i]; cc+=sm[2][i]; d+=sm[3][i]; }
        const float inv = 1.f / (float)HD;
        float mc = a * inv, mp = cc * inv;
        float vc = b2 * inv - mc * mc;
        float vp = d  * inv - mp * mp;
        stats[0] = mc; stats[1] = rsqrtf(vc + LN_EPS);
        stats[2] = mp; stats[3] = rsqrtf(vp + LN_EPS);
    }
    __syncthreads();
    const float mc = stats[0], rc = stats[1], mp = stats[2], rp = stats[3];

    uint2* oA = (uint2*)(outA + (size_t)row * HD);
    uint2* oB = (uint2*)(outB + (size_t)row * HD);
    const float4* g4  = (const float4*)gam;
    const float4* b4  = (const float4*)bet;
    const float4* a4  = (const float4*)mA;
    const float4* m4  = (const float4*)mB;

#pragma unroll
    for (int i = 0; i < 2; i++) {
        const int idx = tid + i * 256;
        const float4 gv = g4[idx], bv = b4[idx], av = a4[idx], mv = m4[idx];
        const float4 cv = c[i], pv = p[i];
        float4 ra, rb;
#define DO_COMP(F)                                                           \
        {                                                                    \
            float h  = (cv.F - mc) * rc * gv.F + bv.F;                       \
            float hh = hasPrev ? ((pv.F - mp) * rp * gv.F + bv.F) : 0.f;     \
            ra.F = h * av.F + hh * (1.f - av.F);                             \
            rb.F = h * mv.F + hh * (1.f - mv.F);                             \
        }
        DO_COMP(x) DO_COMP(y) DO_COMP(z) DO_COMP(w)
#undef DO_COMP
        oA[idx] = cvt4h(ra); oB[idx] = cvt4h(rb);
    }
}

// ---------------------------------------------------------------------------
// fp16 mma.sync GEMM: C[M,N] = A[M,K] @ B[N,K]^T  (M = 8192 fixed)
// CTA 256x128x32, 16 warps (4x4), warp tile 64x32, 3-stage cp.async.
// Per-thread mainloop identical to the proven R6 kernel; only the CTA shape
// changed (more MMA work per barrier per SMSP). GY=8 L2 tile swizzle.
// ---------------------------------------------------------------------------
enum { EP_NONE = 0, EP_SILU = 1, EP_SIGMUL = 2, EP_ADD = 3, EP_SIGMUL_ADD = 4 };

template <int EP, typename OutT>
__global__ __launch_bounds__(512, 1) void gemm_mma(
    const __half* __restrict__ A, const __half* __restrict__ B,
    OutT* __restrict__ C, const float* __restrict__ D,
    const float* __restrict__ E, int N, int K, int nn)
{
    extern __shared__ __half smem[];

    const int tid  = threadIdx.x;
    const int warp = tid >> 5;
    const int lane = tid & 31;
    const int g    = lane >> 2;     // 0..7
    const int t    = lane & 3;      // 0..3
    const int wm   = warp & 3;      // 4 warps along M
    const int wn   = warp >> 2;     // 4 warps along N

    // tile mapping with GY=8 group swizzle (M-tiles of 256 rows)
    const int gsz = 8 * nn;
    const int grp = blockIdx.x / gsz;
    const int rem = blockIdx.x % gsz;
    const int mt  = grp * 8 + (rem & 7);
    const int nt  = rem >> 3;
    const size_t brow = (size_t)mt * 256;
    const size_t bcol = (size_t)nt * 128;

    // cp.async: A 256 rows x 64B (2 thr/row x 32B); B 128 rows x 64B (4 thr/row x 16B)
    const int lrowA = tid >> 1;             // 0..255
    const int partA = tid & 1;
    const int lrowB = tid >> 2;             // 0..127
    const int partB = tid & 3;
    const __half* gA = A + (brow + lrowA) * (size_t)K + partA * 16;
    const __half* gB = B + (bcol + lrowB) * (size_t)K + partB * 8;
    const uint32_t smb = smem_u32(smem);
    const uint32_t sa_row = smb + (uint32_t)lrowA * (SPADH * 2) + (uint32_t)partA * 32u;
    const uint32_t sb_row = smb + (uint32_t)(A_STAGE_HALVES * 2)
                                + (uint32_t)lrowB * (SPADH * 2) + (uint32_t)partB * 16u;

    auto load_stage = [&](int s, int c) {
        const uint32_t so = (uint32_t)s * STAGE_BYTES;
        const __half* pa = gA + (size_t)c * 32;
        const __half* pb = gB + (size_t)c * 32;
        CP_ASYNC16(sa_row + so,       pa);
        CP_ASYNC16(sa_row + so + 16u, pa + 8);
        CP_ASYNC16(sb_row + so,       pb);
        asm volatile("cp.async.commit_group;");
    };

    float acc[4][4][4];
#pragma unroll
    for (int i = 0; i < 4; i++)
#pragma unroll
        for (int j = 0; j < 4; j++)
#pragma unroll
            for (int r = 0; r < 4; r++) acc[i][j][r] = 0.f;

    load_stage(0, 0);
    load_stage(1, 1);

    // per-thread fragment base indices (halves)
    const int aTb = (wm * 64 + g) * SPADH + 2 * t;
    const int bTb = (wn * 32 + g) * SPADH + 2 * t;

    const int nch = K >> 5;
    for (int c = 0; c < nch; c++) {
        const int s = c % NST;
        asm volatile("cp.async.wait_group %0;" :: "n"(NST - 2));
        __syncthreads();
        if (c + 2 < nch) load_stage((c + 2) % NST, c + 2);

        const __half* sA = smem + s * STAGE_HALVES;
        const __half* sB = sA + A_STAGE_HALVES;
#pragma unroll
        for (int ks = 0; ks < 2; ks++) {     // two k16 steps per 32-chunk
            uint32_t af[4][4], bf[4][2];
#pragma unroll
            for (int i = 0; i < 4; i++) {
                const __half* p = sA + aTb + i * (16 * SPADH) + ks * 16;
                af[i][0] = *(const uint32_t*)(p);
                af[i][1] = *(const uint32_t*)(p + 8 * SPADH);
                af[i][2] = *(const uint32_t*)(p + 8);
                af[i][3] = *(const uint32_t*)(p + 8 * SPADH + 8);
            }
#pragma unroll
            for (int j = 0; j < 4; j++) {
                const __half* p = sB + bTb + j * (8 * SPADH) + ks * 16;
                bf[j][0] = *(const uint32_t*)(p);
                bf[j][1] = *(const uint32_t*)(p + 8);
            }
#pragma unroll
            for (int i = 0; i < 4; i++)
#pragma unroll
                for (int j = 0; j < 4; j++)
                    MMA_F16(acc[i][j], af[i], bf[j]);
        }
    }
    asm volatile("cp.async.wait_group 0;");

    // ---------------- epilogue: registers -> fused ops -> stores -------------
#pragma unroll
    for (int i = 0; i < 4; i++) {
#pragma unroll
        for (int j = 0; j < 4; j++) {
            const size_t row0 = brow + wm * 64 + i * 16 + g;
            const size_t col  = bcol + wn * 32 + j * 8 + 2 * t;
#pragma unroll
            for (int h = 0; h < 2; h++) {     // h=0: rows g, h=1: rows g+8
                const size_t gi = (row0 + h * 8) * (size_t)N + col;
                float v0 = acc[i][j][2 * h + 0];
                float v1 = acc[i][j][2 * h + 1];
                float2 o;
                if (EP == EP_NONE) {
                    o = make_float2(v0, v1);
                } else if (EP == EP_SILU) {
                    o = make_float2(v0 / (1.f + __expf(-v0)),
                                    v1 / (1.f + __expf(-v1)));
                } else if (EP == EP_SIGMUL) {
                    const float2 dv = *(const float2*)(D + gi);
                    o = make_float2(dv.x / (1.f + __expf(-v0)),
                                    dv.y / (1.f + __expf(-v1)));
                } else if (EP == EP_ADD) {
                    const float2 dv = *(const float2*)(D + gi);
                    o = make_float2(v0 + dv.x, v1 + dv.y);
                } else { // EP_SIGMUL_ADD
                    const float2 dv = *(const float2*)(D + gi);
                    const float2 ev = *(const float2*)(E + gi);
                    o = make_float2(dv.x / (1.f + __expf(-v0)) + ev.x,
                                    dv.y / (1.f + __expf(-v1)) + ev.y);
                }
                if (sizeof(OutT) == 2) {
                    __half2 hv = __floats2half2_rn(o.x, o.y);
                    *(__half2*)((__half*)C + gi) = hv;
                } else {
                    *(float2*)((float*)C + gi) = o;
                }
            }
        }
    }
}

// ---------------------------------------------------------------------------
// Launch sequence.  (wkv_run with aa=bb=0, pp=-1e38 reduces exactly to wkv=v,
// so k / Wk / tm_first / tm_decay are dead and the Wk GEMM is skipped.)
// ---------------------------------------------------------------------------
extern "C" void kernel_launch(void* const* d_in, const int* in_sizes, int n_in,
                              void* d_out, int out_size)
{
    (void)in_sizes; (void)n_in; (void)out_size;
    const float* x     = (const float*)d_in[0];
    const float* ln1_g = (const float*)d_in[1];
    const float* ln1_b = (const float*)d_in[2];
    const float* ln2_g = (const float*)d_in[3];
    const float* ln2_b = (const float*)d_in[4];
    const float* tm_mv = (const float*)d_in[8];
    const float* tm_mr = (const float*)d_in[9];
    const float* Wv    = (const float*)d_in[11];
    const float* Wr    = (const float*)d_in[12];
    const float* Wo    = (const float*)d_in[13];
    const float* cm_mk = (const float*)d_in[14];
    const float* cm_mr = (const float*)d_in[15];
    const float* Wkey  = (const float*)d_in[16];
    const float* Wval  = (const float*)d_in[17];
    const float* Wcr   = (const float*)d_in[18];
    float* out = (float*)d_out;

    float *s0, *s2, *s3;
    __half *h0, *h1, *h2, *h3, *bigh;
    __half *hWv, *hWr, *hWo, *hWcr, *hWkey, *hWval;
    cudaGetSymbolAddress((void**)&s0, g_s0);
    cudaGetSymbolAddress((void**)&s2, g_s2);
    cudaGetSymbolAddress((void**)&s3, g_s3);
    cudaGetSymbolAddress((void**)&h0, g_h0);
    cudaGetSymbolAddress((void**)&h1, g_h1);
    cudaGetSymbolAddress((void**)&h2, g_h2);
    cudaGetSymbolAddress((void**)&h3, g_h3);
    cudaGetSymbolAddress((void**)&bigh, g_bigh);
    cudaGetSymbolAddress((void**)&hWv, g_hWv);
    cudaGetSymbolAddress((void**)&hWr, g_hWr);
    cudaGetSymbolAddress((void**)&hWo, g_hWo);
    cudaGetSymbolAddress((void**)&hWcr, g_hWcr);
    cudaGetSymbolAddress((void**)&hWkey, g_hWkey);
    cudaGetSymbolAddress((void**)&hWval, g_hWval);

    cudaFuncSetAttribute((const void*)gemm_mma<EP_NONE, float>,
                         cudaFuncAttributeMaxDynamicSharedMemorySize, SMEM_BYTES);
    cudaFuncSetAttribute((const void*)gemm_mma<EP_SILU, __half>,
                         cudaFuncAttributeMaxDynamicSharedMemorySize, SMEM_BYTES);
    cudaFuncSetAttribute((const void*)gemm_mma<EP_SIGMUL, __half>,
                         cudaFuncAttributeMaxDynamicSharedMemorySize, SMEM_BYTES);
    cudaFuncSetAttribute((const void*)gemm_mma<EP_ADD, float>,
                         cudaFuncAttributeMaxDynamicSharedMemorySize, SMEM_BYTES);
    cudaFuncSetAttribute((const void*)gemm_mma<EP_SIGMUL_ADD, float>,
                         cudaFuncAttributeMaxDynamicSharedMemorySize, SMEM_BYTES);

    // convert weights fp32 -> fp16 (2 launches)
    PtrTab pt;
    pt.s0 = (const float4*)Wv;  pt.d0 = (uint2*)hWv;
    pt.s1 = (const float4*)Wr;  pt.d1 = (uint2*)hWr;
    pt.s2 = (const float4*)Wo;  pt.d2 = (uint2*)hWo;
    pt.s3 = (const float4*)Wcr; pt.d3 = (uint2*)hWcr;
    conv_sq<<<(4 << 20) / 256, 256>>>(pt);
    conv_big<<<(8 << 20) / 256, 256>>>((const float4*)Wkey, (uint2*)hWkey,
                                       (const float4*)Wval, (uint2*)hWval);

    const dim3 blk(512);
    const int nmT = NROWS / 256;           // 32
    const int nnSq = HD / 128;             // 16
    const int nnBg = H4 / 128;             // 64
    const dim3 gSq(nmT * nnSq);            // 512 CTAs
    const dim3 gBg(nmT * nnBg);            // 2048 CTAs

    // --- time-mix ---
    ln_mix_kernel<<<NROWS, 256>>>(x, ln1_g, ln1_b, tm_mv, tm_mr, h0, h1);
    // v = xv @ Wv^T  (fp32, used elementwise)
    gemm_mma<EP_NONE, float><<<gSq, blk, SMEM_BYTES>>>(h0, hWv, s2, nullptr, nullptr, HD, HD, nnSq);
    // u = sigmoid(xr @ Wr^T) * v  -> fp16 (feeds Wo GEMM)
    gemm_mma<EP_SIGMUL, __half><<<gSq, blk, SMEM_BYTES>>>(h1, hWr, h3, s2, nullptr, HD, HD, nnSq);
    // x1 = u @ Wo^T + x  (fp32 residual)
    gemm_mma<EP_ADD, float><<<gSq, blk, SMEM_BYTES>>>(h3, hWo, s0, x, nullptr, HD, HD, nnSq);

    // --- channel-mix ---
    ln_mix_kernel<<<NROWS, 256>>>(s0, ln2_g, ln2_b, cm_mk, cm_mr, h1, h2);
    // silu(xk2 @ Wkey^T) -> fp16 (feeds Wval GEMM)
    gemm_mma<EP_SILU, __half><<<gBg, blk, SMEM_BYTES>>>(h1, hWkey, bigh, nullptr, nullptr, H4, HD, nnBg);
    // kv = big @ Wval^T  (fp32, used elementwise)
    gemm_mma<EP_NONE, float><<<gSq, blk, SMEM_BYTES>>>(bigh, hWval, s3, nullptr, nullptr, HD, H4, nnSq);
    // out = sigmoid(xr2 @ Wcr^T) * kv + x1
    gemm_mma<EP_SIGMUL_ADD, float><<<gSq, blk, SMEM_BYTES>>>(h2, hWcr, out, s3, s0, HD, H4 / 4, nnSq);
}

// round 11
// speedup vs baseline: 1.6778x; 1.1073x over previous
#include <cuda_runtime.h>
#include <cuda_fp16.h>
#include <cstdint>

// ---------------------------------------------------------------------------
// Problem constants
// ---------------------------------------------------------------------------
#define HD    2048
#define SEQ   2048
#define NROWS 8192            // B*T
#define H4    8192            // 4*HD
#define LN_EPS 1e-5f

// GEMM tiling: 128x128 CTA tile, K-chunk 32 halves, 3-stage cp.async
#define NST 3
#define SPADH 40                          // smem row stride in halves (conflict-free)
#define STAGE_HALVES (2 * 128 * SPADH)    // A tile + B tile = 10240 halves
#define STAGE_BYTES  (STAGE_HALVES * 2)   // 20480
#define SMEM_BYTES   (NST * STAGE_BYTES)  // 61440 (2 CTAs/SM)

// ---------------------------------------------------------------------------
// Scratch (device globals — no allocation allowed)
// ---------------------------------------------------------------------------
__device__ __align__(256) float  g_s0[(size_t)NROWS * HD];
__device__ __align__(256) float  g_s2[(size_t)NROWS * HD];
__device__ __align__(256) float  g_s3[(size_t)NROWS * HD];
__device__ __align__(256) __half g_h0[(size_t)NROWS * HD];
__device__ __align__(256) __half g_h1[(size_t)NROWS * HD];
__device__ __align__(256) __half g_h2[(size_t)NROWS * HD];
__device__ __align__(256) __half g_h3[(size_t)NROWS * HD];
__device__ __align__(256) __half g_bigh[(size_t)NROWS * H4];   // 128 MB
// fp16 weight copies
__device__ __align__(256) __half g_hWv[(size_t)HD * HD];
__device__ __align__(256) __half g_hWr[(size_t)HD * HD];
__device__ __align__(256) __half g_hWo[(size_t)HD * HD];
__device__ __align__(256) __half g_hWcr[(size_t)HD * HD];
__device__ __align__(256) __half g_hWkey[(size_t)H4 * HD];
__device__ __align__(256) __half g_hWval[(size_t)HD * H4];

// ---------------------------------------------------------------------------
// Helpers
// ---------------------------------------------------------------------------
__device__ __forceinline__ uint32_t smem_u32(const void* p) {
    uint32_t a;
    asm("{ .reg .u64 t; cvta.to.shared.u64 t, %1; cvt.u32.u64 %0, t; }"
        : "=r"(a) : "l"(p));
    return a;
}

#define MMA_F16(d, a, b)                                                     \
    asm volatile(                                                            \
        "mma.sync.aligned.m16n8k16.row.col.f32.f16.f16.f32 "                 \
        "{%0,%1,%2,%3}, {%4,%5,%6,%7}, {%8,%9}, {%0,%1,%2,%3};"              \
        : "+f"((d)[0]), "+f"((d)[1]), "+f"((d)[2]), "+f"((d)[3])             \
        : "r"((a)[0]), "r"((a)[1]), "r"((a)[2]), "r"((a)[3]),                \
          "r"((b)[0]), "r"((b)[1]))

#define CP_ASYNC16(dst, src) \
    asm volatile("cp.async.cg.shared.global [%0], [%1], 16;" :: "r"(dst), "l"(src))

__device__ __forceinline__ uint2 cvt4h(float4 v) {
    __half2 lo = __floats2half2_rn(v.x, v.y);
    __half2 hi = __floats2half2_rn(v.z, v.w);
    uint2 r;
    r.x = *(uint32_t*)&lo; r.y = *(uint32_t*)&hi;
    return r;
}

// ---------------------------------------------------------------------------
// Weight conversion fp32 -> fp16 (2 merged launches)
// ---------------------------------------------------------------------------
struct PtrTab {
    const float4* s0; const float4* s1; const float4* s2; const float4* s3;
    uint2* d0; uint2* d1; uint2* d2; uint2* d3;
};

__global__ __launch_bounds__(256) void conv_sq(PtrTab p) {
    const int idx = blockIdx.x * 256 + threadIdx.x;   // 4 x 1M float4
    const int which = idx >> 20;
    const int off = idx & 0xFFFFF;
    const float4* s; uint2* d;
    if (which == 0)      { s = p.s0; d = p.d0; }
    else if (which == 1) { s = p.s1; d = p.d1; }
    else if (which == 2) { s = p.s2; d = p.d2; }
    else                 { s = p.s3; d = p.d3; }
    d[off] = cvt4h(s[off]);
}

__global__ __launch_bounds__(256) void conv_big(const float4* __restrict__ sA,
                                                uint2* __restrict__ dA,
                                                const float4* __restrict__ sB,
                                                uint2* __restrict__ dB) {
    const int idx = blockIdx.x * 256 + threadIdx.x;   // 2 x 4M float4
    const int which = idx >> 22;
    const int off = idx & 0x3FFFFF;
    const float4* s = which ? sB : sA;
    uint2* d = which ? dB : dA;
    d[off] = cvt4h(s[off]);
}

// ---------------------------------------------------------------------------
// LayerNorm + time-shift + two mixes -> fp16 outputs (feed GEMMs only)
// ---------------------------------------------------------------------------
__global__ __launch_bounds__(256) void ln_mix_kernel(
    const float* __restrict__ X, const float* __restrict__ gam,
    const float* __restrict__ bet, const float* __restrict__ mA,
    const float* __restrict__ mB, __half* __restrict__ outA,
    __half* __restrict__ outB)
{
    const int row = blockIdx.x;
    const int t   = row & (SEQ - 1);
    const int tid = threadIdx.x;
    const bool hasPrev = (t != 0);

    const float4* xr = (const float4*)(X + (size_t)row * HD);
    const float4* xp = (const float4*)(X + (size_t)(row - 1) * HD);

    float4 c[2], p[2];
    c[0] = xr[tid]; c[1] = xr[tid + 256];
    if (hasPrev) { p[0] = xp[tid]; p[1] = xp[tid + 256]; }
    else { p[0] = make_float4(0.f,0.f,0.f,0.f); p[1] = p[0]; }

    float sc = 0.f, qc = 0.f, sp = 0.f, qp = 0.f;
#pragma unroll
    for (int i = 0; i < 2; i++) {
        sc += c[i].x + c[i].y + c[i].z + c[i].w;
        qc += c[i].x*c[i].x + c[i].y*c[i].y + c[i].z*c[i].z + c[i].w*c[i].w;
        sp += p[i].x + p[i].y + p[i].z + p[i].w;
        qp += p[i].x*p[i].x + p[i].y*p[i].y + p[i].z*p[i].z + p[i].w*p[i].w;
    }
#pragma unroll
    for (int o = 16; o; o >>= 1) {
        sc += __shfl_xor_sync(0xffffffffu, sc, o);
        qc += __shfl_xor_sync(0xffffffffu, qc, o);
        sp += __shfl_xor_sync(0xffffffffu, sp, o);
        qp += __shfl_xor_sync(0xffffffffu, qp, o);
    }
    __shared__ float sm[4][8];
    __shared__ float stats[4];
    const int warp = tid >> 5, lane = tid & 31;
    if (lane == 0) { sm[0][warp]=sc; sm[1][warp]=qc; sm[2][warp]=sp; sm[3][warp]=qp; }
    __syncthreads();
    if (tid == 0) {
        float a=0.f, b2=0.f, cc=0.f, d=0.f;
#pragma unroll
        for (int i = 0; i < 8; i++) { a+=sm[0][i]; b2+=sm[1][i]; cc+=sm[2][i]; d+=sm[3][i]; }
        const float inv = 1.f / (float)HD;
        float mc = a * inv, mp = cc * inv;
        float vc = b2 * inv - mc * mc;
        float vp = d  * inv - mp * mp;
        stats[0] = mc; stats[1] = rsqrtf(vc + LN_EPS);
        stats[2] = mp; stats[3] = rsqrtf(vp + LN_EPS);
    }
    __syncthreads();
    const float mc = stats[0], rc = stats[1], mp = stats[2], rp = stats[3];

    uint2* oA = (uint2*)(outA + (size_t)row * HD);
    uint2* oB = (uint2*)(outB + (size_t)row * HD);
    const float4* g4  = (const float4*)gam;
    const float4* b4  = (const float4*)bet;
    const float4* a4  = (const float4*)mA;
    const float4* m4  = (const float4*)mB;

#pragma unroll
    for (int i = 0; i < 2; i++) {
        const int idx = tid + i * 256;
        const float4 gv = g4[idx], bv = b4[idx], av = a4[idx], mv = m4[idx];
        const float4 cv = c[i], pv = p[i];
        float4 ra, rb;
#define DO_COMP(F)                                                           \
        {                                                                    \
            float h  = (cv.F - mc) * rc * gv.F + bv.F;                       \
            float hh = hasPrev ? ((pv.F - mp) * rp * gv.F + bv.F) : 0.f;     \
            ra.F = h * av.F + hh * (1.f - av.F);                             \
            rb.F = h * mv.F + hh * (1.f - mv.F);                             \
        }
        DO_COMP(x) DO_COMP(y) DO_COMP(z) DO_COMP(w)
#undef DO_COMP
        oA[idx] = cvt4h(ra); oB[idx] = cvt4h(rb);
    }
}

// ---------------------------------------------------------------------------
// fp16 mma.sync GEMM: C[M,N] = A[M,K] @ B[N,K]^T  (M = 8192 fixed)
// CTA 128x128x32, 3-stage cp.async, 8 warps (2x4), warp tile 64x32.
// R6 structure; single change: BOTH k16-steps' fragments are loaded in one
// burst before any MMA, so the second LDS burst drains under MMA execution.
// ---------------------------------------------------------------------------
enum { EP_NONE = 0, EP_SILU = 1, EP_SIGMUL = 2, EP_ADD = 3, EP_SIGMUL_ADD = 4 };

template <int EP, typename OutT>
__global__ __launch_bounds__(256, 2) void gemm_mma(
    const __half* __restrict__ A, const __half* __restrict__ B,
    OutT* __restrict__ C, const float* __restrict__ D,
    const float* __restrict__ E, int N, int K, int nn)
{
    extern __shared__ __half smem[];

    const int tid  = threadIdx.x;
    const int warp = tid >> 5;
    const int lane = tid & 31;
    const int g    = lane >> 2;     // 0..7
    const int t    = lane & 3;      // 0..3
    const int wm   = warp & 1;      // 2 warps along M
    const int wn   = warp >> 1;     // 4 warps along N

    // tile mapping with GY=8 group swizzle
    const int gsz = 8 * nn;
    const int grp = blockIdx.x / gsz;
    const int rem = blockIdx.x % gsz;
    const int mt  = grp * 8 + (rem & 7);
    const int nt  = rem >> 3;
    const size_t brow = (size_t)mt * 128;
    const size_t bcol = (size_t)nt * 128;

    // cp.async: tile row = 64B; each thread does 2x16B for A, 2x16B for B
    const int lrow = tid >> 1;              // 0..127
    const int part = tid & 1;               // half-row: 0 or 1
    const __half* gA = A + (brow + lrow) * (size_t)K + part * 16;
    const __half* gB = B + (bcol + lrow) * (size_t)K + part * 16;
    const uint32_t smb = smem_u32(smem);
    const uint32_t sa_row = smb + (uint32_t)lrow * (SPADH * 2) + (uint32_t)part * 32u;
    const uint32_t sb_row = sa_row + 128u * (SPADH * 2);

    auto load_stage = [&](int s, int c) {
        const uint32_t so = (uint32_t)s * STAGE_BYTES;
        const __half* pa = gA + (size_t)c * 32;
        const __half* pb = gB + (size_t)c * 32;
        CP_ASYNC16(sa_row + so,       pa);
        CP_ASYNC16(sa_row + so + 16u, pa + 8);
        CP_ASYNC16(sb_row + so,       pb);
        CP_ASYNC16(sb_row + so + 16u, pb + 8);
        asm volatile("cp.async.commit_group;");
    };

    float acc[4][4][4];
#pragma unroll
    for (int i = 0; i < 4; i++)
#pragma unroll
        for (int j = 0; j < 4; j++)
#pragma unroll
            for (int r = 0; r < 4; r++) acc[i][j][r] = 0.f;

    load_stage(0, 0);
    load_stage(1, 1);

    // per-thread fragment base indices (halves)
    const int aTb = (wm * 64 + g) * SPADH + 2 * t;
    const int bTb = (wn * 32 + g) * SPADH + 2 * t;

    const int nch = K >> 5;
    for (int c = 0; c < nch; c++) {
        const int s = c % NST;
        // Drain this chunk's cp.async group. Final iterations must drain fully
        // (wait_group(1) on the last group would be a no-op -> race).
        if (c + 1 < nch) asm volatile("cp.async.wait_group 1;");
        else             asm volatile("cp.async.wait_group 0;");
        __syncthreads();
        if (c + 2 < nch) load_stage((c + 2) % NST, c + 2);

        const __half* sA = smem + s * STAGE_HALVES;
        const __half* sB = sA + 128 * SPADH;

        // Load BOTH k16-steps' fragments first (one 48-LDS burst)...
        uint32_t af[2][4][4], bf[2][4][2];
#pragma unroll
        for (int ks = 0; ks < 2; ks++) {
#pragma unroll
            for (int i = 0; i < 4; i++) {
                const __half* p = sA + aTb + i * (16 * SPADH) + ks * 16;
                af[ks][i][0] = *(const uint32_t*)(p);
                af[ks][i][1] = *(const uint32_t*)(p + 8 * SPADH);
                af[ks][i][2] = *(const uint32_t*)(p + 8);
                af[ks][i][3] = *(const uint32_t*)(p + 8 * SPADH + 8);
            }
#pragma unroll
            for (int j = 0; j < 4; j++) {
                const __half* p = sB + bTb + j * (8 * SPADH) + ks * 16;
                bf[ks][j][0] = *(const uint32_t*)(p);
                bf[ks][j][1] = *(const uint32_t*)(p + 8);
            }
        }
        // ...then all 32 MMAs; the ks=1 LDS tail drains under the ks=0 MMAs.
#pragma unroll
        for (int ks = 0; ks < 2; ks++)
#pragma unroll
            for (int i = 0; i < 4; i++)
#pragma unroll
                for (int j = 0; j < 4; j++)
                    MMA_F16(acc[i][j], af[ks][i], bf[ks][j]);
    }

    // ---------------- epilogue: registers -> fused ops -> stores -------------
#pragma unroll
    for (int i = 0; i < 4; i++) {
#pragma unroll
        for (int j = 0; j < 4; j++) {
            const size_t row0 = brow + wm * 64 + i * 16 + g;
            const size_t col  = bcol + wn * 32 + j * 8 + 2 * t;
#pragma unroll
            for (int h = 0; h < 2; h++) {     // h=0: rows g, h=1: rows g+8
                const size_t gi = (row0 + h * 8) * (size_t)N + col;
                float v0 = acc[i][j][2 * h + 0];
                float v1 = acc[i][j][2 * h + 1];
                float2 o;
                if (EP == EP_NONE) {
                    o = make_float2(v0, v1);
                } else if (EP == EP_SILU) {
                    o = make_float2(v0 / (1.f + __expf(-v0)),
                                    v1 / (1.f + __expf(-v1)));
                } else if (EP == EP_SIGMUL) {
                    const float2 dv = *(const float2*)(D + gi);
                    o = make_float2(dv.x / (1.f + __expf(-v0)),
                                    dv.y / (1.f + __expf(-v1)));
                } else if (EP == EP_ADD) {
                    const float2 dv = *(const float2*)(D + gi);
                    o = make_float2(v0 + dv.x, v1 + dv.y);
                } else { // EP_SIGMUL_ADD: D * sigmoid(acc) ... acc=rr: D/(1+e^-acc)+E
                    const float2 dv = *(const float2*)(D + gi);
                    const float2 ev = *(const float2*)(E + gi);
                    o = make_float2(dv.x / (1.f + __expf(-v0)) + ev.x,
                                    dv.y / (1.f + __expf(-v1)) + ev.y);
                }
                if (sizeof(OutT) == 2) {
                    __half2 hv = __floats2half2_rn(o.x, o.y);
                    *(__half2*)((__half*)C + gi) = hv;
                } else {
                    *(float2*)((float*)C + gi) = o;
                }
            }
        }
    }
}

// ---------------------------------------------------------------------------
// Launch sequence.  (wkv_run with aa=bb=0, pp=-1e38 reduces exactly to wkv=v,
// so k / Wk / tm_first / tm_decay are dead and the Wk GEMM is skipped.)
// ---------------------------------------------------------------------------
extern "C" void kernel_launch(void* const* d_in, const int* in_sizes, int n_in,
                              void* d_out, int out_size)
{
    (void)in_sizes; (void)n_in; (void)out_size;
    const float* x     = (const float*)d_in[0];
    const float* ln1_g = (const float*)d_in[1];
    const float* ln1_b = (const float*)d_in[2];
    const float* ln2_g = (const float*)d_in[3];
    const float* ln2_b = (const float*)d_in[4];
    const float* tm_mv = (const float*)d_in[8];
    const float* tm_mr = (const float*)d_in[9];
    const float* Wv    = (const float*)d_in[11];
    const float* Wr    = (const float*)d_in[12];
    const float* Wo    = (const float*)d_in[13];
    const float* cm_mk = (const float*)d_in[14];
    const float* cm_mr = (const float*)d_in[15];
    const float* Wkey  = (const float*)d_in[16];
    const float* Wval  = (const float*)d_in[17];
    const float* Wcr   = (const float*)d_in[18];
    float* out = (float*)d_out;

    float *s0, *s2, *s3;
    __half *h0, *h1, *h2, *h3, *bigh;
    __half *hWv, *hWr, *hWo, *hWcr, *hWkey, *hWval;
    cudaGetSymbolAddress((void**)&s0, g_s0);
    cudaGetSymbolAddress((void**)&s2, g_s2);
    cudaGetSymbolAddress((void**)&s3, g_s3);
    cudaGetSymbolAddress((void**)&h0, g_h0);
    cudaGetSymbolAddress((void**)&h1, g_h1);
    cudaGetSymbolAddress((void**)&h2, g_h2);
    cudaGetSymbolAddress((void**)&h3, g_h3);
    cudaGetSymbolAddress((void**)&bigh, g_bigh);
    cudaGetSymbolAddress((void**)&hWv, g_hWv);
    cudaGetSymbolAddress((void**)&hWr, g_hWr);
    cudaGetSymbolAddress((void**)&hWo, g_hWo);
    cudaGetSymbolAddress((void**)&hWcr, g_hWcr);
    cudaGetSymbolAddress((void**)&hWkey, g_hWkey);
    cudaGetSymbolAddress((void**)&hWval, g_hWval);

    cudaFuncSetAttribute((const void*)gemm_mma<EP_NONE, float>,
                         cudaFuncAttributeMaxDynamicSharedMemorySize, SMEM_BYTES);
    cudaFuncSetAttribute((const void*)gemm_mma<EP_SILU, __half>,
                         cudaFuncAttributeMaxDynamicSharedMemorySize, SMEM_BYTES);
    cudaFuncSetAttribute((const void*)gemm_mma<EP_SIGMUL, __half>,
                         cudaFuncAttributeMaxDynamicSharedMemorySize, SMEM_BYTES);
    cudaFuncSetAttribute((const void*)gemm_mma<EP_ADD, float>,
                         cudaFuncAttributeMaxDynamicSharedMemorySize, SMEM_BYTES);
    cudaFuncSetAttribute((const void*)gemm_mma<EP_SIGMUL_ADD, float>,
                         cudaFuncAttributeMaxDynamicSharedMemorySize, SMEM_BYTES);

    // convert weights fp32 -> fp16 (2 launches)
    PtrTab pt;
    pt.s0 = (const float4*)Wv;  pt.d0 = (uint2*)hWv;
    pt.s1 = (const float4*)Wr;  pt.d1 = (uint2*)hWr;
    pt.s2 = (const float4*)Wo;  pt.d2 = (uint2*)hWo;
    pt.s3 = (const float4*)Wcr; pt.d3 = (uint2*)hWcr;
    conv_sq<<<(4 << 20) / 256, 256>>>(pt);
    conv_big<<<(8 << 20) / 256, 256>>>((const float4*)Wkey, (uint2*)hWkey,
                                       (const float4*)Wval, (uint2*)hWval);

    const dim3 blk(256);
    const int nmT = NROWS / 128;           // 64
    const int nnSq = HD / 128;             // 16
    const int nnBg = H4 / 128;             // 64
    const dim3 gSq(nmT * nnSq);            // 1024 CTAs
    const dim3 gBg(nmT * nnBg);            // 4096 CTAs

    // --- time-mix ---
    ln_mix_kernel<<<NROWS, blk>>>(x, ln1_g, ln1_b, tm_mv, tm_mr, h0, h1);
    // v = xv @ Wv^T  (fp32, used elementwise)
    gemm_mma<EP_NONE, float><<<gSq, blk, SMEM_BYTES>>>(h0, hWv, s2, nullptr, nullptr, HD, HD, nnSq);
    // u = sigmoid(xr @ Wr^T) * v  -> fp16 (feeds Wo GEMM)
    gemm_mma<EP_SIGMUL, __half><<<gSq, blk, SMEM_BYTES>>>(h1, hWr, h3, s2, nullptr, HD, HD, nnSq);
    // x1 = u @ Wo^T + x  (fp32 residual)
    gemm_mma<EP_ADD, float><<<gSq, blk, SMEM_BYTES>>>(h3, hWo, s0, x, nullptr, HD, HD, nnSq);

    // --- channel-mix ---
    ln_mix_kernel<<<NROWS, blk>>>(s0, ln2_g, ln2_b, cm_mk, cm_mr, h1, h2);
    // silu(xk2 @ Wkey^T) -> fp16 (feeds Wval GEMM)
    gemm_mma<EP_SILU, __half><<<gBg, blk, SMEM_BYTES>>>(h1, hWkey, bigh, nullptr, nullptr, H4, HD, nnBg);
    // kv = big @ Wval^T  (fp32, used elementwise)
    gemm_mma<EP_NONE, float><<<gSq, blk, SMEM_BYTES>>>(bigh, hWval, s3, nullptr, nullptr, HD, H4, nnSq);
    // out = kv * sigmoid(xr2 @ Wcr^T) + x1
    gemm_mma<EP_SIGMUL_ADD, float><<<gSq, blk, SMEM_BYTES>>>(h2, hWcr, out, s3, s0, HD, HD, nnSq);
}